// round 8
// baseline (speedup 1.0000x reference)
#include <cuda_runtime.h>

// x: [32, 256, 64, 64] f32; weight: [256, 256, 3, 3] f32; bias: [256] f32
// out: [32, 256, 1, 1] f32   (spatial = 128*128 = 16384)
#define B_   32
#define C_   256
#define O_   256
#define HW_  4096            // 64*64
#define BC_  (B_ * C_)       // 8192

// Kernel-B tiling
#define OT_  8               // o's per block
#define QC_  16              // channels per block
#define NOT_ (O_ / OT_)      // 32 o-tiles
#define NQ_  (C_ / QC_)      // 16 channel-tiles
// grid B = NOT_ * NQ_ = 512 blocks

// Scratch (no allocations). g_done zero-init at load; reset per launch.
__device__ float g_statsT[C_][B_][4];         // [c][b] -> (T, R0, C0, x00)
__device__ float g_part[NOT_][NQ_][OT_][B_];  // partial sums
__device__ unsigned int g_done[NOT_ * 32];    // 1 counter per o-tile, line-padded

// ---------------------------------------------------------------------------
// Kernel A: per-(b,c) image stats. One block per 16 KB image, 256 threads,
// 4x float4 per thread (__ldcs streaming). 134 MB read — the roofline kernel.
// ---------------------------------------------------------------------------
__global__ void __launch_bounds__(256) stats_kernel(const float* __restrict__ x) {
    const int bc = blockIdx.x;
    const float4* __restrict__ p4 =
        reinterpret_cast<const float4*>(x + (size_t)bc * HW_);
    const int t = threadIdx.x;

    float s = 0.f, r0 = 0.f, c0 = 0.f, v00 = 0.f;

    #pragma unroll
    for (int i = 0; i < 4; i++) {
        const int j = t + i * 256;        // float4 index 0..1023
        float4 v = __ldcs(&p4[j]);
        float vs = v.x + v.y + v.z + v.w;
        s += vs;
        if (j < 16)          r0 += vs;    // row 0 = first 64 elems
        if ((j & 15) == 0)   c0 += v.x;   // col 0 = elem % 64 == 0
        if (j == 0)          v00 = v.x;
    }

    #pragma unroll
    for (int off = 16; off > 0; off >>= 1) {
        s  += __shfl_xor_sync(0xFFFFFFFFu, s,  off);
        r0 += __shfl_xor_sync(0xFFFFFFFFu, r0, off);
        c0 += __shfl_xor_sync(0xFFFFFFFFu, c0, off);
    }

    __shared__ float ss[8], sr[8], sc[8];
    __shared__ float sv00;
    const int warp = t >> 5, lane = t & 31;
    if (t == 0) sv00 = v00;
    if (lane == 0) { ss[warp] = s; sr[warp] = r0; sc[warp] = c0; }
    __syncthreads();

    if (warp == 0) {
        float fs = (lane < 8) ? ss[lane] : 0.f;
        float fr = (lane < 8) ? sr[lane] : 0.f;
        float fc = (lane < 8) ? sc[lane] : 0.f;
        #pragma unroll
        for (int off = 4; off > 0; off >>= 1) {
            fs += __shfl_xor_sync(0xFFFFFFFFu, fs, off);
            fr += __shfl_xor_sync(0xFFFFFFFFu, fr, off);
            fc += __shfl_xor_sync(0xFFFFFFFFu, fc, off);
        }
        if (lane == 0) {
            const int b = bc >> 8;
            const int c = bc & 255;
            float4* dst = reinterpret_cast<float4*>(&g_statsT[c][b][0]);
            *dst = make_float4(fs, fr, fc, sv00);
        }
    }
}

// ---------------------------------------------------------------------------
// Kernel B: tiled micro-GEMM with inline weight folding.
// grid = (o-tile, q) = 32*16 = 512 blocks, 256 threads.
//   phase 0: threads 0..127 fold raw weights for their (c,o) pair -> smem
//            (each (c,o) belongs to exactly ONE block: no redundancy)
//   phase 1: thread = (o_local = t>>5, b = t&31); 16-channel dot4,
//            stats loads coalesced in b and L1-shared across the 8 o-warps
//   phase 2: partial to g_part (coalesced), last block per o-tile combines
//            16 partials in fixed order + epilogue 2*(S/16384 + bias)
// ---------------------------------------------------------------------------
__global__ void __launch_bounds__(256) gemm_kernel(const float* __restrict__ w,
                                                   const float* __restrict__ bias,
                                                   float* __restrict__ out) {
    const int ot = blockIdx.x >> 4;        // / NQ_
    const int q  = blockIdx.x & (NQ_ - 1);
    const int t  = threadIdx.x;
    const int obase = ot * OT_;
    const int cbase = q * QC_;

    __shared__ float4 wsm[QC_ * OT_];      // [c_local][o_local]
    __shared__ unsigned int s_old;

    // ---- phase 0: fold weights (threads 0..127, one (c,o) pair each) ----
    if (t < QC_ * OT_) {
        const int c_l = t >> 3;            // / OT_
        const int o_l = t & (OT_ - 1);
        const float* p = w + ((size_t)(cbase + c_l) * O_ + (obase + o_l)) * 9;
        float w00 = __ldg(p + 0), w01 = __ldg(p + 1), w02 = __ldg(p + 2);
        float w10 = __ldg(p + 3), w11 = __ldg(p + 4), w12 = __ldg(p + 5);
        float w20 = __ldg(p + 6), w21 = __ldg(p + 7), w22 = __ldg(p + 8);
        float wsum = ((w00 + w01) + (w02 + w10)) + ((w11 + w12) + (w20 + w21)) + w22;
        float wkh0 = w00 + w01 + w02;      // kh == 0 row
        float wkw0 = w00 + w10 + w20;      // kw == 0 col
        wsm[t] = make_float4(wsum, -wkh0, -wkw0, w00);
    }
    __syncthreads();

    // ---- phase 1: 16-channel partial dot ----
    const int o_l = t >> 5;                // warp = local o
    const int b   = t & 31;                // lane = batch

    float acc0 = 0.f, acc1 = 0.f;
    #pragma unroll
    for (int k = 0; k < QC_; k += 2) {
        const float4 a0 = *reinterpret_cast<const float4*>(&g_statsT[cbase + k][b][0]);
        const float4 w0 = wsm[k * OT_ + o_l];
        const float4 a1 = *reinterpret_cast<const float4*>(&g_statsT[cbase + k + 1][b][0]);
        const float4 w1 = wsm[(k + 1) * OT_ + o_l];
        acc0 = fmaf(a0.x, w0.x, acc0);
        acc1 = fmaf(a1.x, w1.x, acc1);
        acc0 = fmaf(a0.y, w0.y, acc0);
        acc1 = fmaf(a1.y, w1.y, acc1);
        acc0 = fmaf(a0.z, w0.z, acc0);
        acc1 = fmaf(a1.z, w1.z, acc1);
        acc0 = fmaf(a0.w, w0.w, acc0);
        acc1 = fmaf(a1.w, w1.w, acc1);
    }
    g_part[ot][q][o_l][b] = acc0 + acc1;   // coalesced 128 B per warp

    // ---- phase 2: election + combine ----
    __threadfence();
    __syncthreads();
    if (t == 0) s_old = atomicAdd(&g_done[ot * 32], 1u);
    __syncthreads();

    if (s_old == NQ_ - 1u) {               // this block arrived last for ot
        __threadfence();                   // acquire: see all partials
        float s = 0.f;
        #pragma unroll
        for (int qq = 0; qq < NQ_; qq++)   // fixed order -> deterministic
            s += __ldcg(&g_part[ot][qq][o_l][b]);
        const int o = obase + o_l;
        out[b * O_ + o] = 2.0f * (s * (1.0f / 16384.0f) + __ldg(&bias[o]));
        if (t == 0) atomicExch(&g_done[ot * 32], 0u);   // replay-safe reset
    }
}

// ---------------------------------------------------------------------------
extern "C" void kernel_launch(void* const* d_in, const int* in_sizes, int n_in,
                              void* d_out, int out_size) {
    const float* x    = (const float*)d_in[0];
    const float* wgt  = (const float*)d_in[1];
    const float* bias = (const float*)d_in[2];
    float* out        = (float*)d_out;

    stats_kernel<<<BC_, 256>>>(x);
    gemm_kernel<<<NOT_ * NQ_, 256>>>(wgt, bias, out);
}

// round 9
// speedup vs baseline: 1.1041x; 1.1041x over previous
#include <cuda_runtime.h>

// x: [32, 256, 64, 64] f32; weight: [256, 256, 3, 3] f32; bias: [256] f32
// out: [32, 256, 1, 1] f32   (spatial = 128*128 = 16384)
#define B_   32
#define C_   256
#define O_   256
#define HW_  4096            // 64*64
#define BC_  (B_ * C_)       // 8192 stats (producer) blocks

// Consumer tiling: block = (o-tile of 8) x (channel-tile of 16)
#define OT_  8
#define QC_  16
#define NOT_ (O_ / OT_)      // 32
#define NQ_  (C_ / QC_)      // 16
#define NCONS (NOT_ * NQ_)   // 512 consumer blocks
#define NPROD BC_            // 8192 producers
#define NTOTAL (NPROD + NCONS)

// Scratch (no allocations). Counters zero-init at load; every launch resets
// them itself (replay-safe, verified pattern from R4/R8).
__device__ float g_statsT[C_][B_][4];         // [c][b] -> (T, R0, C0, x00)
__device__ float g_part[NOT_][NQ_][OT_][B_];  // partial sums
__device__ unsigned int g_done[NOT_ * 32];    // per-o-tile election ctr (padded)
__device__ unsigned int g_cnt;                // producers completed
__device__ unsigned int g_cnt2;               // consumers past barrier

// release-increment: orders prior global stores, NO CCTL.IVALL (fence scope
// >= cluster is what triggers the L1 flush; red.release does not)
__device__ __forceinline__ void release_count(unsigned int* p) {
    asm volatile("red.release.gpu.add.u32 [%0], %1;" :: "l"(p), "r"(1u) : "memory");
}
__device__ __forceinline__ unsigned int acquire_load(const unsigned int* p) {
    unsigned int v;
    asm volatile("ld.acquire.gpu.u32 %0, [%1];" : "=r"(v) : "l"(p) : "memory");
    return v;
}

// ---------------------------------------------------------------------------
// Single fused launch.
//   blocks [0, 8192)    : per-(b,c) image stats — the 134 MB roofline stream
//   blocks [8192, 8704) : consumers — fold weights (independent of stats,
//                         overlaps the stream tail), spin with backoff,
//                         then 16-channel partial dot + election + epilogue
// ---------------------------------------------------------------------------
__global__ void __launch_bounds__(256) fused_kernel(const float* __restrict__ x,
                                                    const float* __restrict__ w,
                                                    const float* __restrict__ bias,
                                                    float* __restrict__ out) {
    const int t = threadIdx.x;

    if (blockIdx.x < NPROD) {
        // ================= stats producer =================
        const int bc = blockIdx.x;
        const float4* __restrict__ p4 =
            reinterpret_cast<const float4*>(x + (size_t)bc * HW_);

        float s = 0.f, r0 = 0.f, c0 = 0.f, v00 = 0.f;

        #pragma unroll
        for (int i = 0; i < 4; i++) {
            const int j = t + i * 256;        // float4 index 0..1023
            float4 v = __ldcs(&p4[j]);        // streaming, read-once
            float vs = v.x + v.y + v.z + v.w;
            s += vs;
            if (j < 16)          r0 += vs;    // row 0 = first 64 elems
            if ((j & 15) == 0)   c0 += v.x;   // col 0 = elem % 64 == 0
            if (j == 0)          v00 = v.x;
        }

        #pragma unroll
        for (int off = 16; off > 0; off >>= 1) {
            s  += __shfl_xor_sync(0xFFFFFFFFu, s,  off);
            r0 += __shfl_xor_sync(0xFFFFFFFFu, r0, off);
            c0 += __shfl_xor_sync(0xFFFFFFFFu, c0, off);
        }

        __shared__ float ss[8], sr[8], sc[8];
        __shared__ float sv00;
        const int warp = t >> 5, lane = t & 31;
        if (t == 0) sv00 = v00;
        if (lane == 0) { ss[warp] = s; sr[warp] = r0; sc[warp] = c0; }
        __syncthreads();

        if (warp == 0) {
            float fs = (lane < 8) ? ss[lane] : 0.f;
            float fr = (lane < 8) ? sr[lane] : 0.f;
            float fc = (lane < 8) ? sc[lane] : 0.f;
            #pragma unroll
            for (int off = 4; off > 0; off >>= 1) {
                fs += __shfl_xor_sync(0xFFFFFFFFu, fs, off);
                fr += __shfl_xor_sync(0xFFFFFFFFu, fr, off);
                fc += __shfl_xor_sync(0xFFFFFFFFu, fc, off);
            }
            if (lane == 0) {
                const int b = bc >> 8;
                const int c = bc & 255;
                *reinterpret_cast<float4*>(&g_statsT[c][b][0]) =
                    make_float4(fs, fr, fc, sv00);
                release_count(&g_cnt);        // release: no L1 flush
            }
        }
    } else {
        // ================= consumer =================
        const int ci = blockIdx.x - NPROD;
        const int ot = ci >> 4;               // / NQ_
        const int q  = ci & (NQ_ - 1);
        const int obase = ot * OT_;
        const int cbase = q * QC_;

        __shared__ float4 wsm[QC_ * OT_];     // [c_local][o_local]
        __shared__ unsigned int s_old;

        // ---- fold weights BEFORE waiting (independent of stats) ----
        if (t < QC_ * OT_) {
            const int c_l = t >> 3;
            const int o_l = t & (OT_ - 1);
            const float* p = w + ((size_t)(cbase + c_l) * O_ + (obase + o_l)) * 9;
            float w00 = __ldg(p + 0), w01 = __ldg(p + 1), w02 = __ldg(p + 2);
            float w10 = __ldg(p + 3), w11 = __ldg(p + 4), w12 = __ldg(p + 5);
            float w20 = __ldg(p + 6), w21 = __ldg(p + 7), w22 = __ldg(p + 8);
            float wsum = ((w00 + w01) + (w02 + w10)) + ((w11 + w12) + (w20 + w21)) + w22;
            float wkh0 = w00 + w01 + w02;     // kh == 0 row
            float wkw0 = w00 + w10 + w20;     // kw == 0 col
            wsm[t] = make_float4(wsum, -wkh0, -wkw0, w00);
        }
        __syncthreads();

        // ---- spin-wait for all producers (backoff: low L2 poll rate) ----
        if (t == 0) {
            if (acquire_load(&g_cnt) < (unsigned int)NPROD) {
                do { __nanosleep(256); }
                while (acquire_load(&g_cnt) < (unsigned int)NPROD);
            }
        }
        __syncthreads();

        // replay-safe reset of the producer counter (after ALL consumers pass)
        if (t == 0) {
            unsigned int old = atomicAdd(&g_cnt2, 1u);
            if (old == (unsigned int)NCONS - 1u) {
                atomicExch(&g_cnt, 0u);
                atomicExch(&g_cnt2, 0u);
            }
        }

        // ---- 16-channel partial dot: warp = local o, lane = batch ----
        const int o_l = t >> 5;
        const int b   = t & 31;

        float acc0 = 0.f, acc1 = 0.f;
        #pragma unroll
        for (int k = 0; k < QC_; k += 2) {
            const float4 a0 = __ldcg(reinterpret_cast<const float4*>(&g_statsT[cbase + k][b][0]));
            const float4 w0 = wsm[k * OT_ + o_l];
            const float4 a1 = __ldcg(reinterpret_cast<const float4*>(&g_statsT[cbase + k + 1][b][0]));
            const float4 w1 = wsm[(k + 1) * OT_ + o_l];
            acc0 = fmaf(a0.x, w0.x, acc0);
            acc1 = fmaf(a1.x, w1.x, acc1);
            acc0 = fmaf(a0.y, w0.y, acc0);
            acc1 = fmaf(a1.y, w1.y, acc1);
            acc0 = fmaf(a0.z, w0.z, acc0);
            acc1 = fmaf(a1.z, w1.z, acc1);
            acc0 = fmaf(a0.w, w0.w, acc0);
            acc1 = fmaf(a1.w, w1.w, acc1);
        }
        g_part[ot][q][o_l][b] = acc0 + acc1;  // coalesced 128 B per warp

        // ---- election: last block per o-tile combines ----
        __syncthreads();
        if (t == 0) {
            __threadfence();                  // consumers only: stream is done
            s_old = atomicAdd(&g_done[ot * 32], 1u);
        }
        __syncthreads();

        if (s_old == (unsigned int)NQ_ - 1u) {
            float sacc = 0.f;
            #pragma unroll
            for (int qq = 0; qq < NQ_; qq++)  // fixed order -> deterministic
                sacc += __ldcg(&g_part[ot][qq][o_l][b]);
            const int o = obase + o_l;
            out[b * O_ + o] = 2.0f * (sacc * (1.0f / 16384.0f) + __ldg(&bias[o]));
            if (t == 0) atomicExch(&g_done[ot * 32], 0u);   // replay-safe
        }
    }
}

// ---------------------------------------------------------------------------
extern "C" void kernel_launch(void* const* d_in, const int* in_sizes, int n_in,
                              void* d_out, int out_size) {
    const float* x    = (const float*)d_in[0];
    const float* wgt  = (const float*)d_in[1];
    const float* bias = (const float*)d_in[2];
    float* out        = (float*)d_out;

    fused_kernel<<<NTOTAL, 256>>>(x, wgt, bias, out);
}